// round 13
// baseline (speedup 1.0000x reference)
#include <cuda_runtime.h>
#include <cuda_bf16.h>
#include <math.h>
#include <stdint.h>

// ---------------------------------------------------------------------------
// MambaVision block on sm_103a. GEMMs via warp-level mma.sync bf16 (HMMA) +
// ldmatrix + 4-stage cp.async pipeline (tcgen05 unavailable: harness PTX
// targets sm_103 sans 'a'). Chunked parallel scan, 4 pairs/warp (8 lanes per
// pair, 2 states/lane), predicated gating tail.
// B=8, C=384, L=1024, d_inner=768, N=16, dt_rank=24
// ---------------------------------------------------------------------------

#define B_   8
#define C_   384
#define L_   1024
#define DI_  768
#define NS_  16
#define RK_  24
#define XP_  56
#define NT_  (B_ * L_)   // 8192 tokens
#define NCH_ 8           // scan chunks
#define TCH_ 128         // steps per chunk

// ---------------- scratch ----------------
__device__ __nv_bfloat16 g_tok_bf [NT_ * C_];       // LN output, bf16
__device__ float         g_xin    [NT_ * DI_];      // in_proj x-half fp32
__device__ __nv_bfloat16 g_z_bf   [NT_ * DI_];      // in_proj z-half bf16
__device__ float2        g_dtu    [NT_ * DI_];      // (.x=softplus dt, .y=u)
__device__ __nv_bfloat16 g_u_bf   [NT_ * DI_];      // conv+silu bf16 (x_proj A)
__device__ float         g_bc     [NT_ * 32];       // interleaved (B_n, C_n) x16
__device__ __nv_bfloat16 g_dtlo_bf[NT_ * 64];       // dt_lo padded to 64, bf16
__device__ __nv_bfloat16 g_y_bf   [NT_ * DI_];      // gated scan out bf16
// scan chunk summaries [pair][chunk][n]
__device__ float g_Hc[B_ * DI_ * NCH_ * NS_];
__device__ float g_Pc[B_ * DI_ * NCH_ * NS_];
__device__ float g_Hi[B_ * DI_ * NCH_ * NS_];
// bf16 weight copies (padded)
__device__ __nv_bfloat16 g_wi_bf[2 * DI_ * C_];     // in_proj_w  [1536,384]
__device__ __nv_bfloat16 g_wx_bf[64 * DI_];         // x_proj_w   [64(pad56),768]
__device__ __nv_bfloat16 g_wd_bf[DI_ * 64];         // dt_proj_w  [768,64(pad24)]
__device__ __nv_bfloat16 g_wo_bf[C_ * DI_];         // out_proj_w [384,768]

// ---------------- helpers ----------------
__device__ __forceinline__ uint32_t smem_u32(const void* p) {
    uint32_t a;
    asm("{ .reg .u64 t; cvta.to.shared.u64 t, %1; cvt.u32.u64 %0, t; }"
        : "=r"(a) : "l"(p));
    return a;
}
__device__ __forceinline__ void cp16(uint32_t dst, const void* src) {
    asm volatile("cp.async.cg.shared.global [%0], [%1], 16;"
                 :: "r"(dst), "l"(src) : "memory");
}
#define CP_COMMIT() asm volatile("cp.async.commit_group;" ::: "memory")

__device__ __forceinline__ void ldsm4(uint32_t* r, uint32_t addr) {
    asm volatile("ldmatrix.sync.aligned.m8n8.x4.shared.b16 {%0,%1,%2,%3}, [%4];"
        : "=r"(r[0]), "=r"(r[1]), "=r"(r[2]), "=r"(r[3]) : "r"(addr));
}
__device__ __forceinline__ void mma16816(float* c, const uint32_t* a,
                                         const uint32_t* b) {
    asm volatile(
        "mma.sync.aligned.m16n8k16.row.col.f32.bf16.bf16.f32 "
        "{%0,%1,%2,%3}, {%4,%5,%6,%7}, {%8,%9}, {%0,%1,%2,%3};"
        : "+f"(c[0]), "+f"(c[1]), "+f"(c[2]), "+f"(c[3])
        : "r"(a[0]), "r"(a[1]), "r"(a[2]), "r"(a[3]), "r"(b[0]), "r"(b[1]));
}

// ---------------------------------------------------------------------------
// LayerNorm -> bf16 tokens. Block of 512 handles 16 tokens.
// ---------------------------------------------------------------------------
__global__ __launch_bounds__(512) void ln_kernel(
    const float* __restrict__ x, const float* __restrict__ lw,
    const float* __restrict__ lb)
{
    __shared__ float tile[C_ * 17];
    int bi = blockIdx.x;
    int b  = bi >> 6;
    int l0 = (bi & 63) << 4;
    int tid = threadIdx.x;

    for (int idx = tid; idx < C_ * 16; idx += 512) {
        int lr = idx & 15, c = idx >> 4;
        tile[c * 17 + lr] = x[(b * C_ + c) * L_ + l0 + lr];
    }
    __syncthreads();

    int w = tid >> 5, lane = tid & 31;
    float s = 0.f, ss = 0.f;
    for (int c = lane; c < C_; c += 32) {
        float v = tile[c * 17 + w];
        s += v; ss += v * v;
    }
    #pragma unroll
    for (int o = 16; o; o >>= 1) {
        s  += __shfl_xor_sync(0xffffffffu, s,  o);
        ss += __shfl_xor_sync(0xffffffffu, ss, o);
    }
    float mean = s * (1.f / C_);
    float rstd = rsqrtf(ss * (1.f / C_) - mean * mean + 1e-5f);

    __nv_bfloat16* orow = g_tok_bf + (size_t)(b * L_ + l0 + w) * C_;
    for (int c = lane; c < C_; c += 32)
        orow[c] = __float2bfloat16((tile[c * 17 + w] - mean) * rstd * lw[c] + lb[c]);
}

// ---------------------------------------------------------------------------
// All four weight converts (fp32 -> bf16, zero-padded) in one kernel.
// ---------------------------------------------------------------------------
#define WI_N (2 * DI_ * C_)    // 589824
#define WX_N (64 * DI_)        // 49152
#define WD_N (DI_ * 64)        // 49152
#define WO_N (C_ * DI_)        // 294912
__global__ __launch_bounds__(256) void cvt_weights(
    const float* __restrict__ wi, const float* __restrict__ wx,
    const float* __restrict__ wd, const float* __restrict__ wo)
{
    int i = blockIdx.x * 256 + threadIdx.x;
    if (i < WI_N) {
        g_wi_bf[i] = __float2bfloat16(wi[i]);
        return;
    }
    i -= WI_N;
    if (i < WX_N) {
        int r = i / DI_, k = i - r * DI_;
        g_wx_bf[i] = __float2bfloat16(r < XP_ ? wx[r * DI_ + k] : 0.f);
        return;
    }
    i -= WX_N;
    if (i < WD_N) {
        int r = i >> 6, k = i & 63;
        g_wd_bf[i] = __float2bfloat16(k < RK_ ? wd[r * RK_ + k] : 0.f);
        return;
    }
    i -= WD_N;
    if (i < WO_N) g_wo_bf[i] = __float2bfloat16(wo[i]);
}

// ---------------------------------------------------------------------------
// Scratch init (also keeps in_proj gemm in the ncu capture slot).
// ---------------------------------------------------------------------------
__global__ __launch_bounds__(256) void init_scratch()
{
    int i = blockIdx.x * 256 + threadIdx.x;
    if (i < B_ * DI_ * NCH_ * NS_) g_Hi[i] = 0.f;
}

// ---------------------------------------------------------------------------
// mma.sync GEMM: C[M,N] = A[M,K] @ W[N,K]^T  (bf16 in, fp32 accum)
// BM x NTILE block tile, 8 warps (2m x 4n), BK=32, 4-stage cp.async pipeline,
// ONE __syncthreads per K-iter. Smem rows padded to 80B (LDSM conflict-free).
// mode 0: plain fp32 store
// mode 1: + bias + softplus -> interleaved g_dtu.x  (Cout = (float*)g_dtu)
// mode 2: aux bf16 dt_lo (col<24, pad 64) + interleaved B|C into g_bc
// mode 3: out fused transpose + residual: Cout[(b,c,l)] = v + resid[(b,c,l)]
// mode 4: in_proj split: cols<DI_ -> fp32 Cout; cols>=DI_ -> bf16 aux
// ---------------------------------------------------------------------------
template<int BM, int NTILE>
__global__ __launch_bounds__(256) void gemm_mma(
    const __nv_bfloat16* __restrict__ A, const __nv_bfloat16* __restrict__ Bw,
    int K, float* __restrict__ Cout, int ldc, int mode,
    const float* __restrict__ bias, __nv_bfloat16* __restrict__ aux,
    const float* __restrict__ resid)
{
    constexpr int WN    = NTILE / 4;   // warp n-width
    constexpr int NFRAG = WN / 8;
    constexpr int MI    = BM / 32;     // 16-row m-frags per warp
    constexpr int AST   = BM * 80;     // A bytes per stage (80B/row)
    constexpr int BST   = NTILE * 80;

    extern __shared__ __align__(128) char smem[];
    uint32_t a_base = smem_u32(smem);
    uint32_t b_base = a_base + 4 * AST;

    int tid = threadIdx.x, wid = tid >> 5, lane = tid & 31;
    int wm = wid >> 2, wn = wid & 3;
    int m0 = blockIdx.y * BM, n0 = blockIdx.x * NTILE;

    float c[MI][NFRAG][4];
    #pragma unroll
    for (int mi = 0; mi < MI; mi++)
        #pragma unroll
        for (int ni = 0; ni < NFRAG; ni++)
            #pragma unroll
            for (int q = 0; q < 4; q++) c[mi][ni][q] = 0.f;

    auto load_tile = [&](int it, int s) {
        int k0 = it * 32;
        #pragma unroll
        for (int rep = 0; rep < BM / 64; rep++) {
            int ch = tid + rep * 256;          // BM*4 chunks of 16B for A
            int row = ch >> 2, seg = ch & 3;
            cp16(a_base + s * AST + row * 80 + seg * 16,
                 (const char*)(A + (size_t)(m0 + row) * K + k0) + seg * 16);
        }
        #pragma unroll
        for (int rep = 0; rep < (NTILE == 128 ? 2 : 1); rep++) {
            int ch = tid + rep * 256;          // NTILE*4 chunks for B
            int row = ch >> 2, seg = ch & 3;
            cp16(b_base + s * BST + row * 80 + seg * 16,
                 (const char*)(Bw + (size_t)(n0 + row) * K + k0) + seg * 16);
        }
    };

    const int NC = K >> 5;   // K / 32
    #pragma unroll
    for (int s = 0; s < 3; s++) {
        if (s < NC) load_tile(s, s);
        CP_COMMIT();
    }

    int lq = lane >> 3, lr = lane & 7;   // ldsm4 B addressing
    for (int it = 0; it < NC; it++) {
        asm volatile("cp.async.wait_group 2;" ::: "memory");
        __syncthreads();
        int pf = it + 3;
        if (pf < NC) load_tile(pf, pf & 3);
        CP_COMMIT();

        int s = it & 3;
        uint32_t abuf = a_base + s * AST;
        uint32_t bbuf = b_base + s * BST;
        #pragma unroll
        for (int kc = 0; kc < 2; kc++) {
            uint32_t a_frag[MI][4];
            uint32_t arow = abuf + (wm * (BM / 2) + (lane & 15)) * 80
                          + kc * 32 + (lane >> 4) * 16;
            #pragma unroll
            for (int mi = 0; mi < MI; mi++)
                ldsm4(a_frag[mi], arow + mi * 16 * 80);

            // B: one ldsm4 covers 2 n-frags x 2 k-halves
            uint32_t b_frag[NFRAG][2];
            #pragma unroll
            for (int bn = 0; bn < NFRAG; bn += 2) {
                uint32_t addr = bbuf
                    + (wn * WN + bn * 8 + (lq >> 1) * 8 + lr) * 80
                    + kc * 32 + (lq & 1) * 16;
                ldsm4(&b_frag[bn][0], addr);
            }

            #pragma unroll
            for (int mi = 0; mi < MI; mi++)
                #pragma unroll
                for (int ni = 0; ni < NFRAG; ni++)
                    mma16816(c[mi][ni], a_frag[mi], b_frag[ni]);
        }
    }

    // epilogue
    int g = lane >> 2, tq = lane & 3;
    #pragma unroll
    for (int mi = 0; mi < MI; mi++) {
        #pragma unroll
        for (int ni = 0; ni < NFRAG; ni++) {
            #pragma unroll
            for (int half = 0; half < 2; half++) {
                int row = m0 + wm * (BM / 2) + mi * 16 + g + half * 8;
                int col = n0 + wn * WN + ni * 8 + tq * 2;
                float v0 = c[mi][ni][half * 2];
                float v1 = c[mi][ni][half * 2 + 1];
                if (mode == 0) {
                    *(float2*)&Cout[(size_t)row * ldc + col] = make_float2(v0, v1);
                } else if (mode == 1) {
                    float s0 = v0 + bias[col];
                    float s1 = v1 + bias[col + 1];
                    s0 = (s0 > 20.f) ? s0 : log1pf(__expf(s0));
                    s1 = (s1 > 20.f) ? s1 : log1pf(__expf(s1));
                    float* dst = &Cout[((size_t)row * DI_ + col) * 2];
                    dst[0] = s0;        // .x of g_dtu[row*DI_+col]
                    dst[2] = s1;        // .x of g_dtu[row*DI_+col+1]
                } else if (mode == 2) {
                    #pragma unroll
                    for (int q = 0; q < 2; q++) {
                        int cc = col + q;
                        float v = q ? v1 : v0;
                        aux[(size_t)row * 64 + cc] =
                            __float2bfloat16(cc < RK_ ? v : 0.f);
                        if (cc >= RK_ && cc < RK_ + NS_)
                            Cout[(size_t)row * 32 + (cc - RK_) * 2] = v;
                        else if (cc >= RK_ + NS_ && cc < XP_)
                            Cout[(size_t)row * 32 + (cc - RK_ - NS_) * 2 + 1] = v;
                    }
                } else if (mode == 3) {
                    int b = row >> 10, l = row & (L_ - 1);
                    size_t o0 = (size_t)(b * C_ + col) * L_ + l;
                    size_t o1 = o0 + L_;
                    Cout[o0] = v0 + resid[o0];
                    Cout[o1] = v1 + resid[o1];
                } else { // mode 4
                    if (n0 < DI_) {
                        *(float2*)&Cout[(size_t)row * DI_ + col] =
                            make_float2(v0, v1);
                    } else {
                        __nv_bfloat162 p = __floats2bfloat162_rn(v0, v1);
                        *(__nv_bfloat162*)&aux[(size_t)row * DI_ + col - DI_] = p;
                    }
                }
            }
        }
    }
}

// ---------------------------------------------------------------------------
// causal depthwise conv1d (w=4) + bias + SiLU -> g_dtu.y (fp32) and bf16
// ---------------------------------------------------------------------------
__global__ __launch_bounds__(256) void conv_silu_kernel(
    const float* __restrict__ cw, const float* __restrict__ cb)
{
    int idx = blockIdx.x * 256 + threadIdx.x;
    if (idx >= NT_ * DI_) return;
    int d = idx % DI_;
    int t = idx / DI_;
    int l = t & (L_ - 1);

    float s = cb[d];
    const float* xrow = g_xin + (size_t)t * DI_ + d;
    #pragma unroll
    for (int k = 0; k < 4; k++) {
        int ls = l - 3 + k;
        if (ls >= 0) s += xrow[(ls - l) * DI_] * cw[d * 4 + k];
    }
    float sig = 1.f / (1.f + __expf(-s));
    float u = s * sig;
    ((float*)g_dtu)[(size_t)idx * 2 + 1] = u;   // .y only (.x owned by dt_proj)
    g_u_bf[idx] = __float2bfloat16(u);
}

// ---------------------------------------------------------------------------
// Parallel selective scan, 3 phases. Warp owns FOUR (pair,chunk) units:
// 8 lanes per pair, 2 states per lane (n = q, q+8). Butterfly reduce over
// 8-lane groups (xor 4/2/1); predicated gating tail on lane q==0.
// ---------------------------------------------------------------------------
__global__ __launch_bounds__(512) void scan_phase1(const float* __restrict__ A_log)
{
    int warp = threadIdx.x >> 5, lane = threadIdx.x & 31;
    int sub = lane >> 3, q = lane & 7;
    int gi = (blockIdx.x * 16 + warp) * 4 + sub;
    int ch = gi / (B_ * DI_);
    int pair = gi - ch * (B_ * DI_);
    int b = pair / DI_, d = pair - b * DI_;

    const float L2E = 1.44269504f;
    float An0 = -__expf(A_log[d * NS_ + q]) * L2E;
    float An1 = -__expf(A_log[d * NS_ + q + 8]) * L2E;
    int t0 = ch * TCH_;

    const float2* dtu_p = g_dtu + (size_t)(b * L_ + t0) * DI_ + d;
    const float2* bc_p  = (const float2*)g_bc + (size_t)(b * L_ + t0) * 16 + q;

    float h0 = 0.f, h1 = 0.f, P0 = 1.f, P1 = 1.f;
    #pragma unroll 4
    for (int t = 0; t < TCH_; t++) {
        float2 du = __ldg(dtu_p);
        float2 b0 = __ldg(bc_p);
        float2 b1 = __ldg(bc_p + 8);
        float a0 = exp2f(du.x * An0);
        float a1 = exp2f(du.x * An1);
        float tx = du.x * du.y;
        h0 = h0 * a0 + tx * b0.x;
        h1 = h1 * a1 + tx * b1.x;
        P0 *= a0; P1 *= a1;
        dtu_p += DI_; bc_p += 16;
    }
    int o = (pair * NCH_ + ch) * NS_;
    g_Hc[o + q]     = h0;
    g_Hc[o + q + 8] = h1;
    g_Pc[o + q]     = P0;
    g_Pc[o + q + 8] = P1;
}

__global__ __launch_bounds__(256) void scan_phase2()
{
    int i = blockIdx.x * 256 + threadIdx.x;
    if (i >= B_ * DI_ * NS_) return;
    int pair = i >> 4, n = i & 15;
    float h = 0.f;
    #pragma unroll
    for (int c = 0; c < NCH_; c++) {
        int o = (pair * NCH_ + c) * NS_ + n;
        g_Hi[o] = h;
        h = g_Pc[o] * h + g_Hc[o];
    }
}

__global__ __launch_bounds__(512) void scan_phase3(
    const float* __restrict__ A_log, const float* __restrict__ Dp)
{
    int warp = threadIdx.x >> 5, lane = threadIdx.x & 31;
    int sub = lane >> 3, q = lane & 7;
    int gi = (blockIdx.x * 16 + warp) * 4 + sub;
    int ch = gi / (B_ * DI_);
    int pair = gi - ch * (B_ * DI_);
    int b = pair / DI_, d = pair - b * DI_;

    const float L2E = 1.44269504f;
    float An0 = -__expf(A_log[d * NS_ + q]) * L2E;
    float An1 = -__expf(A_log[d * NS_ + q + 8]) * L2E;
    float Dv = Dp[d];
    int t0 = ch * TCH_;

    const float2* dtu_p = g_dtu + (size_t)(b * L_ + t0) * DI_ + d;
    const float2* bc_p  = (const float2*)g_bc + (size_t)(b * L_ + t0) * 16 + q;
    const __nv_bfloat16* z_p = g_z_bf + (size_t)(b * L_ + t0) * DI_ + d;
    __nv_bfloat16* y_p = g_y_bf + (size_t)(b * L_ + t0) * DI_ + d;

    int o = (pair * NCH_ + ch) * NS_;
    float h0 = g_Hi[o + q];
    float h1 = g_Hi[o + q + 8];

    #pragma unroll 4
    for (int t = 0; t < TCH_; t++) {
        float2 du = __ldg(dtu_p);
        float2 b0 = __ldg(bc_p);
        float2 b1 = __ldg(bc_p + 8);

        float a0 = exp2f(du.x * An0);
        float a1 = exp2f(du.x * An1);
        float tx = du.x * du.y;
        h0 = h0 * a0 + tx * b0.x;
        h1 = h1 * a1 + tx * b1.x;

        float y = h0 * b0.y + h1 * b1.y;
        y += __shfl_xor_sync(0xffffffffu, y, 4);
        y += __shfl_xor_sync(0xffffffffu, y, 2);
        y += __shfl_xor_sync(0xffffffffu, y, 1);

        if (q == 0) {
            float z   = __bfloat162float(*z_p);
            float sig = 1.f / (1.f + __expf(-z));
            y_p[0] = __float2bfloat16((y + du.y * Dv) * (z * sig));
        }
        dtu_p += DI_; bc_p += 16; z_p += DI_; y_p += DI_;
    }
}

// ---------------------------------------------------------------------------
extern "C" void kernel_launch(void* const* d_in, const int* in_sizes, int n_in,
                              void* d_out, int out_size)
{
    const float* x          = (const float*)d_in[0];
    const float* ln_w       = (const float*)d_in[1];
    const float* ln_b       = (const float*)d_in[2];
    const float* in_proj_w  = (const float*)d_in[3];
    const float* conv_w     = (const float*)d_in[4];
    const float* conv_b     = (const float*)d_in[5];
    const float* x_proj_w   = (const float*)d_in[6];
    const float* dt_proj_w  = (const float*)d_in[7];
    const float* dt_proj_b  = (const float*)d_in[8];
    const float* A_log      = (const float*)d_in[9];
    const float* Dp         = (const float*)d_in[10];
    const float* out_proj_w = (const float*)d_in[11];
    float* out = (float*)d_out;

    __nv_bfloat16 *p_tok, *p_ubf, *p_ybf, *p_dtlo, *p_zbf;
    __nv_bfloat16 *p_wi, *p_wx, *p_wd, *p_wo;
    float *p_xin, *p_bc;
    float2 *p_dtu;
    cudaGetSymbolAddress((void**)&p_tok,  g_tok_bf);
    cudaGetSymbolAddress((void**)&p_xin,  g_xin);
    cudaGetSymbolAddress((void**)&p_zbf,  g_z_bf);
    cudaGetSymbolAddress((void**)&p_dtu,  g_dtu);
    cudaGetSymbolAddress((void**)&p_ubf,  g_u_bf);
    cudaGetSymbolAddress((void**)&p_bc,   g_bc);
    cudaGetSymbolAddress((void**)&p_dtlo, g_dtlo_bf);
    cudaGetSymbolAddress((void**)&p_ybf,  g_y_bf);
    cudaGetSymbolAddress((void**)&p_wi,   g_wi_bf);
    cudaGetSymbolAddress((void**)&p_wx,   g_wx_bf);
    cudaGetSymbolAddress((void**)&p_wd,   g_wd_bf);
    cudaGetSymbolAddress((void**)&p_wo,   g_wo_bf);

    const int SZ128 = 4 * (128 * 80 + 128 * 80);  // 81920
    const int SZ64  = 4 * (64 * 80 + 64 * 80);    // 40960
    cudaFuncSetAttribute((const void*)gemm_mma<128, 128>,
                         cudaFuncAttributeMaxDynamicSharedMemorySize, SZ128);
    cudaFuncSetAttribute((const void*)gemm_mma<64, 64>,
                         cudaFuncAttributeMaxDynamicSharedMemorySize, SZ64);

    // 1. LN -> bf16 tokens
    ln_kernel<<<NT_ / 16, 512>>>(x, ln_w, ln_b);

    // 2. weight converts (bf16, padded)
    const int WTOT = WI_N + WX_N + WD_N + WO_N;
    cvt_weights<<<(WTOT + 255) / 256, 256>>>(in_proj_w, x_proj_w, dt_proj_w, out_proj_w);

    // 3. scratch init (keeps in_proj in the ncu capture slot)
    init_scratch<<<(B_ * DI_ * NCH_ * NS_ + 255) / 256, 256>>>();

    // 4. in_proj: [8192,384] x [1536,384]^T -> x fp32 | z bf16 (mode 4)
    gemm_mma<128, 128><<<dim3(2 * DI_ / 128, NT_ / 128), 256, SZ128>>>(
        p_tok, p_wi, C_, p_xin, DI_, 4, nullptr, p_zbf, nullptr);

    // 5. conv + SiLU -> g_dtu.y + g_u_bf
    conv_silu_kernel<<<(NT_ * DI_ + 255) / 256, 256>>>(conv_w, conv_b);

    // 6. x_proj: [8192,768] x [64,768]^T -> dt_lo bf16 + interleaved B|C (mode 2)
    gemm_mma<64, 64><<<dim3(1, NT_ / 64), 256, SZ64>>>(
        p_ubf, p_wx, DI_, p_bc, 32, 2, nullptr, p_dtlo, nullptr);

    // 7. dt_proj + softplus -> g_dtu.x (mode 1)
    gemm_mma<128, 128><<<dim3(DI_ / 128, NT_ / 128), 256, SZ128>>>(
        p_dtlo, p_wd, 64, (float*)p_dtu, DI_, 1, dt_proj_b, nullptr, nullptr);

    // 8. parallel selective scan (+ D skip + gate) -> bf16 y
    scan_phase1<<<(B_ * DI_ * NCH_) / 64, 512>>>(A_log);
    scan_phase2<<<(B_ * DI_ * NS_ + 255) / 256, 256>>>();
    scan_phase3<<<(B_ * DI_ * NCH_) / 64, 512>>>(A_log, Dp);

    // 9. out_proj + transpose + residual (mode 3): [8192,768] x [384,768]^T
    gemm_mma<128, 128><<<dim3(C_ / 128, NT_ / 128), 256, SZ128>>>(
        p_ybf, p_wo, DI_, out, C_, 3, nullptr, nullptr, x);
}

// round 14
// speedup vs baseline: 1.4135x; 1.4135x over previous
#include <cuda_runtime.h>
#include <cuda_bf16.h>
#include <math.h>
#include <stdint.h>

// ---------------------------------------------------------------------------
// MambaVision block on sm_103a. GEMMs via warp-level mma.sync bf16 (HMMA) +
// ldmatrix + 4-stage cp.async pipeline (tcgen05 unavailable: harness PTX
// targets sm_103 sans 'a'). Chunked parallel scan, 4 pairs/warp (8 lanes per
// pair, 2 states/lane), predicated gating tail, MUFU ex2 via inline asm.
// B=8, C=384, L=1024, d_inner=768, N=16, dt_rank=24
// ---------------------------------------------------------------------------

#define B_   8
#define C_   384
#define L_   1024
#define DI_  768
#define NS_  16
#define RK_  24
#define XP_  56
#define NT_  (B_ * L_)   // 8192 tokens
#define NCH_ 8           // scan chunks
#define TCH_ 128         // steps per chunk

// ---------------- scratch ----------------
__device__ __nv_bfloat16 g_tok_bf [NT_ * C_];       // LN output, bf16
__device__ float         g_xin    [NT_ * DI_];      // in_proj x-half fp32
__device__ __nv_bfloat16 g_z_bf   [NT_ * DI_];      // in_proj z-half bf16
__device__ float2        g_dtu    [NT_ * DI_];      // (.x=softplus dt, .y=u)
__device__ __nv_bfloat16 g_u_bf   [NT_ * DI_];      // conv+silu bf16 (x_proj A)
__device__ float         g_bc     [NT_ * 32];       // interleaved (B_n, C_n) x16
__device__ __nv_bfloat16 g_dtlo_bf[NT_ * 64];       // dt_lo padded to 64, bf16
__device__ __nv_bfloat16 g_y_bf   [NT_ * DI_];      // gated scan out bf16
// scan chunk summaries [pair][chunk][n]
__device__ float g_Hc[B_ * DI_ * NCH_ * NS_];
__device__ float g_Pc[B_ * DI_ * NCH_ * NS_];
__device__ float g_Hi[B_ * DI_ * NCH_ * NS_];
// bf16 weight copies (padded)
__device__ __nv_bfloat16 g_wi_bf[2 * DI_ * C_];     // in_proj_w  [1536,384]
__device__ __nv_bfloat16 g_wx_bf[64 * DI_];         // x_proj_w   [64(pad56),768]
__device__ __nv_bfloat16 g_wd_bf[DI_ * 64];         // dt_proj_w  [768,64(pad24)]
__device__ __nv_bfloat16 g_wo_bf[C_ * DI_];         // out_proj_w [384,768]

// ---------------- helpers ----------------
__device__ __forceinline__ uint32_t smem_u32(const void* p) {
    uint32_t a;
    asm("{ .reg .u64 t; cvta.to.shared.u64 t, %1; cvt.u32.u64 %0, t; }"
        : "=r"(a) : "l"(p));
    return a;
}
__device__ __forceinline__ float ex2(float x) {
    float y;
    asm("ex2.approx.f32 %0, %1;" : "=f"(y) : "f"(x));
    return y;
}
__device__ __forceinline__ void cp16(uint32_t dst, const void* src) {
    asm volatile("cp.async.cg.shared.global [%0], [%1], 16;"
                 :: "r"(dst), "l"(src) : "memory");
}
#define CP_COMMIT() asm volatile("cp.async.commit_group;" ::: "memory")

__device__ __forceinline__ void ldsm4(uint32_t* r, uint32_t addr) {
    asm volatile("ldmatrix.sync.aligned.m8n8.x4.shared.b16 {%0,%1,%2,%3}, [%4];"
        : "=r"(r[0]), "=r"(r[1]), "=r"(r[2]), "=r"(r[3]) : "r"(addr));
}
__device__ __forceinline__ void mma16816(float* c, const uint32_t* a,
                                         const uint32_t* b) {
    asm volatile(
        "mma.sync.aligned.m16n8k16.row.col.f32.bf16.bf16.f32 "
        "{%0,%1,%2,%3}, {%4,%5,%6,%7}, {%8,%9}, {%0,%1,%2,%3};"
        : "+f"(c[0]), "+f"(c[1]), "+f"(c[2]), "+f"(c[3])
        : "r"(a[0]), "r"(a[1]), "r"(a[2]), "r"(a[3]), "r"(b[0]), "r"(b[1]));
}

// ---------------------------------------------------------------------------
// LayerNorm -> bf16 tokens. Block of 512 handles 16 tokens.
// ---------------------------------------------------------------------------
__global__ __launch_bounds__(512) void ln_kernel(
    const float* __restrict__ x, const float* __restrict__ lw,
    const float* __restrict__ lb)
{
    __shared__ float tile[C_ * 17];
    int bi = blockIdx.x;
    int b  = bi >> 6;
    int l0 = (bi & 63) << 4;
    int tid = threadIdx.x;

    for (int idx = tid; idx < C_ * 16; idx += 512) {
        int lr = idx & 15, c = idx >> 4;
        tile[c * 17 + lr] = x[(b * C_ + c) * L_ + l0 + lr];
    }
    __syncthreads();

    int w = tid >> 5, lane = tid & 31;
    float s = 0.f, ss = 0.f;
    for (int c = lane; c < C_; c += 32) {
        float v = tile[c * 17 + w];
        s += v; ss += v * v;
    }
    #pragma unroll
    for (int o = 16; o; o >>= 1) {
        s  += __shfl_xor_sync(0xffffffffu, s,  o);
        ss += __shfl_xor_sync(0xffffffffu, ss, o);
    }
    float mean = s * (1.f / C_);
    float rstd = rsqrtf(ss * (1.f / C_) - mean * mean + 1e-5f);

    __nv_bfloat16* orow = g_tok_bf + (size_t)(b * L_ + l0 + w) * C_;
    for (int c = lane; c < C_; c += 32)
        orow[c] = __float2bfloat16((tile[c * 17 + w] - mean) * rstd * lw[c] + lb[c]);
}

// ---------------------------------------------------------------------------
// All four weight converts (fp32 -> bf16, zero-padded) in one kernel.
// ---------------------------------------------------------------------------
#define WI_N (2 * DI_ * C_)    // 589824
#define WX_N (64 * DI_)        // 49152
#define WD_N (DI_ * 64)        // 49152
#define WO_N (C_ * DI_)        // 294912
__global__ __launch_bounds__(256) void cvt_weights(
    const float* __restrict__ wi, const float* __restrict__ wx,
    const float* __restrict__ wd, const float* __restrict__ wo)
{
    int i = blockIdx.x * 256 + threadIdx.x;
    if (i < WI_N) {
        g_wi_bf[i] = __float2bfloat16(wi[i]);
        return;
    }
    i -= WI_N;
    if (i < WX_N) {
        int r = i / DI_, k = i - r * DI_;
        g_wx_bf[i] = __float2bfloat16(r < XP_ ? wx[r * DI_ + k] : 0.f);
        return;
    }
    i -= WX_N;
    if (i < WD_N) {
        int r = i >> 6, k = i & 63;
        g_wd_bf[i] = __float2bfloat16(k < RK_ ? wd[r * RK_ + k] : 0.f);
        return;
    }
    i -= WD_N;
    if (i < WO_N) g_wo_bf[i] = __float2bfloat16(wo[i]);
}

// ---------------------------------------------------------------------------
// Scratch init (also keeps in_proj gemm in the ncu capture slot).
// ---------------------------------------------------------------------------
__global__ __launch_bounds__(256) void init_scratch()
{
    int i = blockIdx.x * 256 + threadIdx.x;
    if (i < B_ * DI_ * NCH_ * NS_) g_Hi[i] = 0.f;
}

// ---------------------------------------------------------------------------
// mma.sync GEMM: C[M,N] = A[M,K] @ W[N,K]^T  (bf16 in, fp32 accum)
// BM x NTILE block tile, 8 warps (2m x 4n), BK=32, 4-stage cp.async pipeline,
// ONE __syncthreads per K-iter. Smem rows padded to 80B (LDSM conflict-free).
// mode 0: plain fp32 store
// mode 1: + bias + softplus -> interleaved g_dtu.x  (Cout = (float*)g_dtu)
// mode 2: aux bf16 dt_lo (col<24, pad 64) + interleaved B|C into g_bc
// mode 3: out fused transpose + residual: Cout[(b,c,l)] = v + resid[(b,c,l)]
// mode 4: in_proj split: cols<DI_ -> fp32 Cout; cols>=DI_ -> bf16 aux
// ---------------------------------------------------------------------------
template<int BM, int NTILE>
__global__ __launch_bounds__(256) void gemm_mma(
    const __nv_bfloat16* __restrict__ A, const __nv_bfloat16* __restrict__ Bw,
    int K, float* __restrict__ Cout, int ldc, int mode,
    const float* __restrict__ bias, __nv_bfloat16* __restrict__ aux,
    const float* __restrict__ resid)
{
    constexpr int WN    = NTILE / 4;   // warp n-width
    constexpr int NFRAG = WN / 8;
    constexpr int MI    = BM / 32;     // 16-row m-frags per warp
    constexpr int AST   = BM * 80;     // A bytes per stage (80B/row)
    constexpr int BST   = NTILE * 80;

    extern __shared__ __align__(128) char smem[];
    uint32_t a_base = smem_u32(smem);
    uint32_t b_base = a_base + 4 * AST;

    int tid = threadIdx.x, wid = tid >> 5, lane = tid & 31;
    int wm = wid >> 2, wn = wid & 3;
    int m0 = blockIdx.y * BM, n0 = blockIdx.x * NTILE;

    float c[MI][NFRAG][4];
    #pragma unroll
    for (int mi = 0; mi < MI; mi++)
        #pragma unroll
        for (int ni = 0; ni < NFRAG; ni++)
            #pragma unroll
            for (int q = 0; q < 4; q++) c[mi][ni][q] = 0.f;

    auto load_tile = [&](int it, int s) {
        int k0 = it * 32;
        #pragma unroll
        for (int rep = 0; rep < BM / 64; rep++) {
            int ch = tid + rep * 256;          // BM*4 chunks of 16B for A
            int row = ch >> 2, seg = ch & 3;
            cp16(a_base + s * AST + row * 80 + seg * 16,
                 (const char*)(A + (size_t)(m0 + row) * K + k0) + seg * 16);
        }
        #pragma unroll
        for (int rep = 0; rep < (NTILE == 128 ? 2 : 1); rep++) {
            int ch = tid + rep * 256;          // NTILE*4 chunks for B
            int row = ch >> 2, seg = ch & 3;
            cp16(b_base + s * BST + row * 80 + seg * 16,
                 (const char*)(Bw + (size_t)(n0 + row) * K + k0) + seg * 16);
        }
    };

    const int NC = K >> 5;   // K / 32
    #pragma unroll
    for (int s = 0; s < 3; s++) {
        if (s < NC) load_tile(s, s);
        CP_COMMIT();
    }

    int lq = lane >> 3, lr = lane & 7;   // ldsm4 B addressing
    for (int it = 0; it < NC; it++) {
        asm volatile("cp.async.wait_group 2;" ::: "memory");
        __syncthreads();
        int pf = it + 3;
        if (pf < NC) load_tile(pf, pf & 3);
        CP_COMMIT();

        int s = it & 3;
        uint32_t abuf = a_base + s * AST;
        uint32_t bbuf = b_base + s * BST;
        #pragma unroll
        for (int kc = 0; kc < 2; kc++) {
            uint32_t a_frag[MI][4];
            uint32_t arow = abuf + (wm * (BM / 2) + (lane & 15)) * 80
                          + kc * 32 + (lane >> 4) * 16;
            #pragma unroll
            for (int mi = 0; mi < MI; mi++)
                ldsm4(a_frag[mi], arow + mi * 16 * 80);

            // B: one ldsm4 covers 2 n-frags x 2 k-halves
            uint32_t b_frag[NFRAG][2];
            #pragma unroll
            for (int bn = 0; bn < NFRAG; bn += 2) {
                uint32_t addr = bbuf
                    + (wn * WN + bn * 8 + (lq >> 1) * 8 + lr) * 80
                    + kc * 32 + (lq & 1) * 16;
                ldsm4(&b_frag[bn][0], addr);
            }

            #pragma unroll
            for (int mi = 0; mi < MI; mi++)
                #pragma unroll
                for (int ni = 0; ni < NFRAG; ni++)
                    mma16816(c[mi][ni], a_frag[mi], b_frag[ni]);
        }
    }

    // epilogue
    int g = lane >> 2, tq = lane & 3;
    #pragma unroll
    for (int mi = 0; mi < MI; mi++) {
        #pragma unroll
        for (int ni = 0; ni < NFRAG; ni++) {
            #pragma unroll
            for (int half = 0; half < 2; half++) {
                int row = m0 + wm * (BM / 2) + mi * 16 + g + half * 8;
                int col = n0 + wn * WN + ni * 8 + tq * 2;
                float v0 = c[mi][ni][half * 2];
                float v1 = c[mi][ni][half * 2 + 1];
                if (mode == 0) {
                    *(float2*)&Cout[(size_t)row * ldc + col] = make_float2(v0, v1);
                } else if (mode == 1) {
                    float s0 = v0 + bias[col];
                    float s1 = v1 + bias[col + 1];
                    s0 = (s0 > 20.f) ? s0 : log1pf(__expf(s0));
                    s1 = (s1 > 20.f) ? s1 : log1pf(__expf(s1));
                    float* dst = &Cout[((size_t)row * DI_ + col) * 2];
                    dst[0] = s0;        // .x of g_dtu[row*DI_+col]
                    dst[2] = s1;        // .x of g_dtu[row*DI_+col+1]
                } else if (mode == 2) {
                    #pragma unroll
                    for (int q = 0; q < 2; q++) {
                        int cc = col + q;
                        float v = q ? v1 : v0;
                        aux[(size_t)row * 64 + cc] =
                            __float2bfloat16(cc < RK_ ? v : 0.f);
                        if (cc >= RK_ && cc < RK_ + NS_)
                            Cout[(size_t)row * 32 + (cc - RK_) * 2] = v;
                        else if (cc >= RK_ + NS_ && cc < XP_)
                            Cout[(size_t)row * 32 + (cc - RK_ - NS_) * 2 + 1] = v;
                    }
                } else if (mode == 3) {
                    int b = row >> 10, l = row & (L_ - 1);
                    size_t o0 = (size_t)(b * C_ + col) * L_ + l;
                    size_t o1 = o0 + L_;
                    Cout[o0] = v0 + resid[o0];
                    Cout[o1] = v1 + resid[o1];
                } else { // mode 4
                    if (n0 < DI_) {
                        *(float2*)&Cout[(size_t)row * DI_ + col] =
                            make_float2(v0, v1);
                    } else {
                        __nv_bfloat162 p = __floats2bfloat162_rn(v0, v1);
                        *(__nv_bfloat162*)&aux[(size_t)row * DI_ + col - DI_] = p;
                    }
                }
            }
        }
    }
}

// ---------------------------------------------------------------------------
// causal depthwise conv1d (w=4) + bias + SiLU -> g_dtu.y (fp32) and bf16
// ---------------------------------------------------------------------------
__global__ __launch_bounds__(256) void conv_silu_kernel(
    const float* __restrict__ cw, const float* __restrict__ cb)
{
    int idx = blockIdx.x * 256 + threadIdx.x;
    if (idx >= NT_ * DI_) return;
    int d = idx % DI_;
    int t = idx / DI_;
    int l = t & (L_ - 1);

    float s = cb[d];
    const float* xrow = g_xin + (size_t)t * DI_ + d;
    #pragma unroll
    for (int k = 0; k < 4; k++) {
        int ls = l - 3 + k;
        if (ls >= 0) s += xrow[(ls - l) * DI_] * cw[d * 4 + k];
    }
    float sig = 1.f / (1.f + __expf(-s));
    float u = s * sig;
    ((float*)g_dtu)[(size_t)idx * 2 + 1] = u;   // .y only (.x owned by dt_proj)
    g_u_bf[idx] = __float2bfloat16(u);
}

// ---------------------------------------------------------------------------
// Parallel selective scan, 3 phases. Warp owns FOUR (pair,chunk) units:
// 8 lanes per pair, 2 states per lane (n = q, q+8). Butterfly reduce over
// 8-lane groups (xor 4/2/1); predicated gating tail on lane q==0.
// exp via MUFU ex2.approx (An pre-scaled by log2 e).
// ---------------------------------------------------------------------------
__global__ __launch_bounds__(512) void scan_phase1(const float* __restrict__ A_log)
{
    int warp = threadIdx.x >> 5, lane = threadIdx.x & 31;
    int sub = lane >> 3, q = lane & 7;
    int gi = (blockIdx.x * 16 + warp) * 4 + sub;
    int ch = gi / (B_ * DI_);
    int pair = gi - ch * (B_ * DI_);
    int b = pair / DI_, d = pair - b * DI_;

    const float L2E = 1.44269504f;
    float An0 = -__expf(A_log[d * NS_ + q]) * L2E;
    float An1 = -__expf(A_log[d * NS_ + q + 8]) * L2E;
    int t0 = ch * TCH_;

    const float2* dtu_p = g_dtu + (size_t)(b * L_ + t0) * DI_ + d;
    const float2* bc_p  = (const float2*)g_bc + (size_t)(b * L_ + t0) * 16 + q;

    float h0 = 0.f, h1 = 0.f, P0 = 1.f, P1 = 1.f;
    #pragma unroll 4
    for (int t = 0; t < TCH_; t++) {
        float2 du = __ldg(dtu_p);
        float2 b0 = __ldg(bc_p);
        float2 b1 = __ldg(bc_p + 8);
        float a0 = ex2(du.x * An0);
        float a1 = ex2(du.x * An1);
        float tx = du.x * du.y;
        h0 = h0 * a0 + tx * b0.x;
        h1 = h1 * a1 + tx * b1.x;
        P0 *= a0; P1 *= a1;
        dtu_p += DI_; bc_p += 16;
    }
    int o = (pair * NCH_ + ch) * NS_;
    g_Hc[o + q]     = h0;
    g_Hc[o + q + 8] = h1;
    g_Pc[o + q]     = P0;
    g_Pc[o + q + 8] = P1;
}

__global__ __launch_bounds__(256) void scan_phase2()
{
    int i = blockIdx.x * 256 + threadIdx.x;
    if (i >= B_ * DI_ * NS_) return;
    int pair = i >> 4, n = i & 15;
    float h = 0.f;
    #pragma unroll
    for (int c = 0; c < NCH_; c++) {
        int o = (pair * NCH_ + c) * NS_ + n;
        g_Hi[o] = h;
        h = g_Pc[o] * h + g_Hc[o];
    }
}

__global__ __launch_bounds__(512) void scan_phase3(
    const float* __restrict__ A_log, const float* __restrict__ Dp)
{
    int warp = threadIdx.x >> 5, lane = threadIdx.x & 31;
    int sub = lane >> 3, q = lane & 7;
    int gi = (blockIdx.x * 16 + warp) * 4 + sub;
    int ch = gi / (B_ * DI_);
    int pair = gi - ch * (B_ * DI_);
    int b = pair / DI_, d = pair - b * DI_;

    const float L2E = 1.44269504f;
    float An0 = -__expf(A_log[d * NS_ + q]) * L2E;
    float An1 = -__expf(A_log[d * NS_ + q + 8]) * L2E;
    float Dv = Dp[d];
    int t0 = ch * TCH_;

    const float2* dtu_p = g_dtu + (size_t)(b * L_ + t0) * DI_ + d;
    const float2* bc_p  = (const float2*)g_bc + (size_t)(b * L_ + t0) * 16 + q;
    const __nv_bfloat16* z_p = g_z_bf + (size_t)(b * L_ + t0) * DI_ + d;
    __nv_bfloat16* y_p = g_y_bf + (size_t)(b * L_ + t0) * DI_ + d;

    int o = (pair * NCH_ + ch) * NS_;
    float h0 = g_Hi[o + q];
    float h1 = g_Hi[o + q + 8];

    #pragma unroll 4
    for (int t = 0; t < TCH_; t++) {
        float2 du = __ldg(dtu_p);
        float2 b0 = __ldg(bc_p);
        float2 b1 = __ldg(bc_p + 8);

        float a0 = ex2(du.x * An0);
        float a1 = ex2(du.x * An1);
        float tx = du.x * du.y;
        h0 = h0 * a0 + tx * b0.x;
        h1 = h1 * a1 + tx * b1.x;

        float y = h0 * b0.y + h1 * b1.y;
        y += __shfl_xor_sync(0xffffffffu, y, 4);
        y += __shfl_xor_sync(0xffffffffu, y, 2);
        y += __shfl_xor_sync(0xffffffffu, y, 1);

        if (q == 0) {
            float z   = __bfloat162float(*z_p);
            float sig = 1.f / (1.f + __expf(-z));
            y_p[0] = __float2bfloat16((y + du.y * Dv) * (z * sig));
        }
        dtu_p += DI_; bc_p += 16; z_p += DI_; y_p += DI_;
    }
}

// ---------------------------------------------------------------------------
extern "C" void kernel_launch(void* const* d_in, const int* in_sizes, int n_in,
                              void* d_out, int out_size)
{
    const float* x          = (const float*)d_in[0];
    const float* ln_w       = (const float*)d_in[1];
    const float* ln_b       = (const float*)d_in[2];
    const float* in_proj_w  = (const float*)d_in[3];
    const float* conv_w     = (const float*)d_in[4];
    const float* conv_b     = (const float*)d_in[5];
    const float* x_proj_w   = (const float*)d_in[6];
    const float* dt_proj_w  = (const float*)d_in[7];
    const float* dt_proj_b  = (const float*)d_in[8];
    const float* A_log      = (const float*)d_in[9];
    const float* Dp         = (const float*)d_in[10];
    const float* out_proj_w = (const float*)d_in[11];
    float* out = (float*)d_out;

    __nv_bfloat16 *p_tok, *p_ubf, *p_ybf, *p_dtlo, *p_zbf;
    __nv_bfloat16 *p_wi, *p_wx, *p_wd, *p_wo;
    float *p_xin, *p_bc;
    float2 *p_dtu;
    cudaGetSymbolAddress((void**)&p_tok,  g_tok_bf);
    cudaGetSymbolAddress((void**)&p_xin,  g_xin);
    cudaGetSymbolAddress((void**)&p_zbf,  g_z_bf);
    cudaGetSymbolAddress((void**)&p_dtu,  g_dtu);
    cudaGetSymbolAddress((void**)&p_ubf,  g_u_bf);
    cudaGetSymbolAddress((void**)&p_bc,   g_bc);
    cudaGetSymbolAddress((void**)&p_dtlo, g_dtlo_bf);
    cudaGetSymbolAddress((void**)&p_ybf,  g_y_bf);
    cudaGetSymbolAddress((void**)&p_wi,   g_wi_bf);
    cudaGetSymbolAddress((void**)&p_wx,   g_wx_bf);
    cudaGetSymbolAddress((void**)&p_wd,   g_wd_bf);
    cudaGetSymbolAddress((void**)&p_wo,   g_wo_bf);

    const int SZ128 = 4 * (128 * 80 + 128 * 80);  // 81920
    const int SZ64  = 4 * (64 * 80 + 64 * 80);    // 40960
    cudaFuncSetAttribute((const void*)gemm_mma<128, 128>,
                         cudaFuncAttributeMaxDynamicSharedMemorySize, SZ128);
    cudaFuncSetAttribute((const void*)gemm_mma<64, 64>,
                         cudaFuncAttributeMaxDynamicSharedMemorySize, SZ64);

    // 1. LN -> bf16 tokens
    ln_kernel<<<NT_ / 16, 512>>>(x, ln_w, ln_b);

    // 2. weight converts (bf16, padded)
    const int WTOT = WI_N + WX_N + WD_N + WO_N;
    cvt_weights<<<(WTOT + 255) / 256, 256>>>(in_proj_w, x_proj_w, dt_proj_w, out_proj_w);

    // 3. scratch init (keeps in_proj in the ncu capture slot)
    init_scratch<<<(B_ * DI_ * NCH_ * NS_ + 255) / 256, 256>>>();

    // 4. in_proj: [8192,384] x [1536,384]^T -> x fp32 | z bf16 (mode 4)
    gemm_mma<128, 128><<<dim3(2 * DI_ / 128, NT_ / 128), 256, SZ128>>>(
        p_tok, p_wi, C_, p_xin, DI_, 4, nullptr, p_zbf, nullptr);

    // 5. conv + SiLU -> g_dtu.y + g_u_bf
    conv_silu_kernel<<<(NT_ * DI_ + 255) / 256, 256>>>(conv_w, conv_b);

    // 6. x_proj: [8192,768] x [64,768]^T -> dt_lo bf16 + interleaved B|C (mode 2)
    gemm_mma<64, 64><<<dim3(1, NT_ / 64), 256, SZ64>>>(
        p_ubf, p_wx, DI_, p_bc, 32, 2, nullptr, p_dtlo, nullptr);

    // 7. dt_proj + softplus -> g_dtu.x (mode 1)
    gemm_mma<128, 128><<<dim3(DI_ / 128, NT_ / 128), 256, SZ128>>>(
        p_dtlo, p_wd, 64, (float*)p_dtu, DI_, 1, dt_proj_b, nullptr, nullptr);

    // 8. parallel selective scan (+ D skip + gate) -> bf16 y
    scan_phase1<<<(B_ * DI_ * NCH_) / 64, 512>>>(A_log);
    scan_phase2<<<(B_ * DI_ * NS_ + 255) / 256, 256>>>();
    scan_phase3<<<(B_ * DI_ * NCH_) / 64, 512>>>(A_log, Dp);

    // 9. out_proj + transpose + residual (mode 3): [8192,768] x [384,768]^T
    gemm_mma<128, 128><<<dim3(C_ / 128, NT_ / 128), 256, SZ128>>>(
        p_ybf, p_wo, DI_, out, C_, 3, nullptr, nullptr, x);
}